// round 12
// baseline (speedup 1.0000x reference)
#include <cuda_runtime.h>
#include <cuda_bf16.h>
#include <cstdint>

#define NCOL 65536
#define NB 32
#define NPTS 2048

#define OFF1 0
#define OFF2 64
#define OFF3 192
#define OFFH1 1216
#define OFFH2 1728
#define OFFH3 1984
#define NSTAT 2112

#define WOFF_C2 0
#define WOFF_C3 32768
#define WOFF_H1 557056
#define WOFF_H2 688128
#define WOFF_H3 1212416
#define WPL_TOTAL 1343488

// ---- scratch ----
__device__ float d_raw1[(size_t)NCOL * 64];
__device__ float d_raw2[(size_t)NCOL * 128];
__device__ float d_rawh1[(size_t)NCOL * 512];
__device__ float d_rawh2[(size_t)NCOL * 256];
__device__ float d_rawh3[(size_t)NCOL * 128];
__device__ __align__(16) char d_wpl[WPL_TOTAL];
__device__ float d_sum[NSTAT];
__device__ float d_sq[NSTAT];
__device__ unsigned d_gmax[NB * 1024];
__device__ float d_gbn[NB * 1024];
__device__ float d_hvec[NB * 512];
__device__ int d_nv[NB];

__device__ __forceinline__ uint32_t smem_u32(const void* p) {
    uint32_t a;
    asm("{ .reg .u64 t; cvta.to.shared.u64 t, %1; cvt.u32.u64 %0, t; }" : "=r"(a) : "l"(p));
    return a;
}
#define CP16(sa, ga) \
    asm volatile("cp.async.cg.shared.global [%0], [%1], 16;" ::"r"(sa), "l"(ga) : "memory")
#define CPC asm volatile("cp.async.commit_group;" ::: "memory")
#define CPW0 asm volatile("cp.async.wait_group 0;" ::: "memory")

__device__ __forceinline__ void mma16(float c[4], const uint32_t a[4], uint32_t b0,
                                      uint32_t b1) {
    asm volatile(
        "mma.sync.aligned.m16n8k16.row.col.f32.bf16.bf16.f32 "
        "{%0,%1,%2,%3}, {%4,%5,%6,%7}, {%8,%9}, {%0,%1,%2,%3};"
        : "+f"(c[0]), "+f"(c[1]), "+f"(c[2]), "+f"(c[3])
        : "r"(a[0]), "r"(a[1]), "r"(a[2]), "r"(a[3]), "r"(b0), "r"(b1));
}
// fast hi/lo split of a pair: returns {hi_pair, lo_pair}, v0 -> low half slot
__device__ __forceinline__ uint2 split2(float v0, float v1) {
    uint32_t hp;
    asm("cvt.rn.bf16x2.f32 %0, %1, %2;" : "=r"(hp) : "f"(v1), "f"(v0));
    float h0 = __uint_as_float(hp << 16);
    float h1 = __uint_as_float(hp & 0xFFFF0000u);
    uint32_t lp;
    asm("cvt.rn.bf16x2.f32 %0, %1, %2;" : "=r"(lp) : "f"(v1 - h1), "f"(v0 - h0));
    return make_uint2(hp, lp);
}
// merged hi/lo chunk layout: row = 64B, 4 chunks of 16B, chunk pos ^= (row>>1)&3
__device__ __forceinline__ void split16_merged(const float v[16], char* rowbase, int swz3) {
#pragma unroll
    for (int t = 0; t < 4; t++) {
        uint2 p1 = split2(v[2 * t], v[2 * t + 1]);
        uint2 p2 = split2(v[2 * t + 8], v[2 * t + 9]);
        *(uint4*)(rowbase + ((t ^ swz3) << 4)) = make_uint4(p1.x, p2.x, p1.y, p2.y);
    }
}
// convert 8 activations (one half-row of a k16) and store two merged chunks
__device__ __forceinline__ void conv8_sts(float4 px0, float4 px1, const float* sc,
                                          const float* sh, int xo1, int xo2, char* dx,
                                          int grp, int swz3) {
    float v[8];
    float4 sc0 = *(const float4*)(sc + xo1);
    float4 sh0 = *(const float4*)(sh + xo1);
    float4 sc1 = *(const float4*)(sc + xo2);
    float4 sh1 = *(const float4*)(sh + xo2);
    v[0] = fmaxf(fmaf(sc0.x, px0.x, sh0.x), 0.f);
    v[1] = fmaxf(fmaf(sc0.y, px0.y, sh0.y), 0.f);
    v[2] = fmaxf(fmaf(sc0.z, px0.z, sh0.z), 0.f);
    v[3] = fmaxf(fmaf(sc0.w, px0.w, sh0.w), 0.f);
    v[4] = fmaxf(fmaf(sc1.x, px1.x, sh1.x), 0.f);
    v[5] = fmaxf(fmaf(sc1.y, px1.y, sh1.y), 0.f);
    v[6] = fmaxf(fmaf(sc1.z, px1.z, sh1.z), 0.f);
    v[7] = fmaxf(fmaf(sc1.w, px1.w, sh1.w), 0.f);
    uint2 s01 = split2(v[0], v[1]);
    uint2 s45 = split2(v[4], v[5]);
    uint2 s23 = split2(v[2], v[3]);
    uint2 s67 = split2(v[6], v[7]);
    *(uint4*)(dx + (((grp * 2) ^ swz3) << 4)) = make_uint4(s01.x, s45.x, s01.y, s45.y);
    *(uint4*)(dx + (((grp * 2 + 1) ^ swz3) << 4)) = make_uint4(s23.x, s67.x, s23.y, s67.y);
}

// ===== prep: zero counters + split all weights into merged bf16 planes =====
__global__ void prep_kernel(const float* __restrict__ w2, const float* __restrict__ w3,
                            const float* __restrict__ hw1, const float* __restrict__ hw2,
                            const float* __restrict__ hw3, char* __restrict__ dst) {
    int idx = blockIdx.x * 256 + threadIdx.x;
    if (idx < NSTAT) { d_sum[idx] = 0.f; d_sq[idx] = 0.f; }
    if (idx < NB * 1024) d_gmax[idx] = 0u;
    if (idx < NB * 512) d_hvec[idx] = 0.f;
    if (idx < NB) d_nv[idx] = 0;

    const float* W; int lda, woff, Cin; char* d; int li;
    if (idx < 512) { W = w2; lda = 64; woff = 0; Cin = 64; d = dst + WOFF_C2; li = idx; }
    else if (idx < 8704) { W = w3; lda = 128; woff = 0; Cin = 128; d = dst + WOFF_C3; li = idx - 512; }
    else if (idx < 10752) { W = hw1; lda = 1088; woff = 1024; Cin = 64; d = dst + WOFF_H1; li = idx - 8704; }
    else if (idx < 18944) { W = hw2; lda = 512; woff = 0; Cin = 512; d = dst + WOFF_H2; li = idx - 10752; }
    else if (idx < 20992) { W = hw3; lda = 256; woff = 0; Cin = 256; d = dst + WOFF_H3; li = idx - 18944; }
    else return;
    const int TK = Cin >> 4;
    const int m = li / TK, k16 = li % TK;
    const float* src = W + (size_t)m * lda + woff + k16 * 16;
    float v[16];
#pragma unroll
    for (int q = 0; q < 4; q++) {
        float4 f = *(const float4*)(src + q * 4);
        v[q * 4 + 0] = f.x; v[q * 4 + 1] = f.y; v[q * 4 + 2] = f.z; v[q * 4 + 3] = f.w;
    }
    const int row = m & 127;
    char* base = d + (size_t)((m >> 7) * TK + k16) * 8192 + row * 64;
    split16_merged(v, base, (row >> 1) & 3);
}

// conv1: 3 -> 64, transposed out [col][64], fused stats
__global__ void conv1_kernel(const float* __restrict__ pts,
                             const float* __restrict__ w,
                             const float* __restrict__ b) {
    __shared__ float ws[192], bs[64], bsum[64], bsq[64];
    int tid = threadIdx.x;
    if (tid < 192) ws[tid] = w[tid];
    if (tid < 64) { bs[tid] = b[tid]; bsum[tid] = 0.f; bsq[tid] = 0.f; }
    __syncthreads();
    int wid = tid >> 5, lid = tid & 31;
    int colbase = (blockIdx.x * 8 + wid) * 32;
    int bb = colbase >> 11, n = colbase & 2047;
    const float* p = pts + (size_t)bb * 3 * NPTS + n + lid;
    float p0 = p[0], p1 = p[NPTS], p2 = p[2 * NPTS];
    float wa0 = ws[lid * 3], wa1 = ws[lid * 3 + 1], wa2 = ws[lid * 3 + 2];
    float wb0 = ws[(lid + 32) * 3], wb1 = ws[(lid + 32) * 3 + 1], wb2 = ws[(lid + 32) * 3 + 2];
    float ba = bs[lid], bbv = bs[lid + 32];
    float sa = 0.f, qa = 0.f, sb = 0.f, qb = 0.f;
#pragma unroll 8
    for (int c = 0; c < 32; c++) {
        float x = __shfl_sync(0xffffffffu, p0, c);
        float y = __shfl_sync(0xffffffffu, p1, c);
        float z = __shfl_sync(0xffffffffu, p2, c);
        float va = fmaf(wa0, x, fmaf(wa1, y, fmaf(wa2, z, ba)));
        float vb = fmaf(wb0, x, fmaf(wb1, y, fmaf(wb2, z, bbv)));
        d_raw1[(size_t)(colbase + c) * 64 + lid] = va;
        d_raw1[(size_t)(colbase + c) * 64 + 32 + lid] = vb;
        sa += va; qa = fmaf(va, va, qa);
        sb += vb; qb = fmaf(vb, vb, qb);
    }
    atomicAdd(&bsum[lid], sa); atomicAdd(&bsq[lid], qa);
    atomicAdd(&bsum[32 + lid], sb); atomicAdd(&bsq[32 + lid], qb);
    __syncthreads();
    if (tid < 64) {
        atomicAdd(&d_sum[OFF1 + tid], bsum[tid]);
        atomicAdd(&d_sq[OFF1 + tid], bsq[tid]);
    }
}

// ========== flat-pipeline bf16x3 HMMA GEMM ==========
template <bool XRES, bool STORE, bool DOMAX, bool COLBIAS, int TK, int MC>
__global__ void __launch_bounds__(256, 2) mma_kernel(
    const char* __restrict__ wpl, const float* __restrict__ bias,
    const float* __restrict__ gg_, const float* __restrict__ be,
    const float* __restrict__ Xraw, int actoff,
    float* __restrict__ Y, int statoff,
    const float* __restrict__ colbias) {
    extern __shared__ __align__(16) char smem[];
    constexpr int Cin = TK * 16;
    constexpr int Mtot = MC * 128;
    constexpr int NPAIR = TK / 2;
    constexpr int NS = MC * NPAIR;
    constexpr int AOFF = XRES ? (TK * 8192) : 32768;
    const int tid = threadIdx.x;
    const int wid = tid >> 5, lane = tid & 31;
    const int gq = lane >> 2, t4 = lane & 3;
    const int m0 = (wid & 3) * 32;
    const int n0 = (wid >> 2) * 64;
    const int col0 = blockIdx.x * 128;
    const int bb = col0 >> 11;
    const uint32_t aB = smem_u32(smem) + AOFF;
    float* sc_s = (float*)(smem + AOFF + 32768);
    float* sh_s = sc_s + Cin;

    // preamble: stage 0 cp.async
    {
        uint32_t s0 = aB + tid * 64;
        const char* g0 = wpl + tid * 64;
        CP16(s0, g0); CP16(s0 + 16, g0 + 16); CP16(s0 + 32, g0 + 32); CP16(s0 + 48, g0 + 48);
        CPC;
    }

    // inline BN finalize of the input layer
    for (int k = tid; k < Cin; k += 256) {
        float m = d_sum[actoff + k] * (1.0f / NCOL);
        float v = d_sq[actoff + k] * (1.0f / NCOL) - m * m;
        float sc = gg_[k] * rsqrtf(v + 1e-5f);
        sc_s[k] = sc;
        sh_s[k] = fmaf(-m, sc, be[k]);
    }
    __syncthreads();

    const int row = tid & 127;
    const int grp = tid >> 7;
    const int swz3 = (row >> 1) & 3;

    if (XRES) {
        for (int k16 = grp; k16 < TK; k16 += 2) {
            const float* src = Xraw + (size_t)(col0 + row) * Cin + k16 * 16;
            float v[16];
#pragma unroll
            for (int q = 0; q < 4; q++) {
                float4 f = *(const float4*)(src + q * 4);
                float4 sc = *(const float4*)(sc_s + k16 * 16 + q * 4);
                float4 sh = *(const float4*)(sh_s + k16 * 16 + q * 4);
                v[q * 4 + 0] = fmaxf(fmaf(sc.x, f.x, sh.x), 0.f);
                v[q * 4 + 1] = fmaxf(fmaf(sc.y, f.y, sh.y), 0.f);
                v[q * 4 + 2] = fmaxf(fmaf(sc.z, f.z, sh.z), 0.f);
                v[q * 4 + 3] = fmaxf(fmaf(sc.w, f.w, sh.w), 0.f);
            }
            split16_merged(v, smem + k16 * 8192 + row * 64, swz3);
        }
    }

    const float* xsrc = Xraw + (size_t)(col0 + row) * Cin;
    const int xo1 = grp * 4, xo2 = grp * 4 + 8;

    uint32_t aoA[2][2], boB[8];
#pragma unroll
    for (int i = 0; i < 2; i++) {
        const int r1 = m0 + i * 16 + gq, r2 = r1 + 8;
        aoA[i][0] = r1 * 64 + ((t4 ^ ((r1 >> 1) & 3)) << 4);
        aoA[i][1] = r2 * 64 + ((t4 ^ ((r2 >> 1) & 3)) << 4);
    }
#pragma unroll
    for (int j = 0; j < 8; j++) {
        const int rb = n0 + j * 8 + gq;
        boB[j] = rb * 64 + ((t4 ^ ((rb >> 1) & 3)) << 4);
    }

    float c[2][8][4];
#pragma unroll
    for (int i = 0; i < 2; i++)
#pragma unroll
        for (int j = 0; j < 8; j++)
#pragma unroll
            for (int k = 0; k < 4; k++) c[i][j][k] = 0.f;

    float4 px[4];
    if (!XRES) {
        px[0] = *(const float4*)(xsrc + xo1);
        px[1] = *(const float4*)(xsrc + xo2);
        px[2] = *(const float4*)(xsrc + 16 + xo1);
        px[3] = *(const float4*)(xsrc + 16 + xo2);
    }

    for (int g = 0; g < NS; g++) {
        const int s = g % NPAIR;
        if (!XRES) {
            const int kb = s * 32;
            char* dx = smem + (g & 1) * 16384 + row * 64;
            conv8_sts(px[0], px[1], sc_s + kb, sh_s + kb, xo1, xo2, dx, grp, swz3);
            conv8_sts(px[2], px[3], sc_s + kb + 16, sh_s + kb + 16, xo1, xo2, dx + 8192, grp, swz3);
        }
        CPW0;
        __syncthreads();
        if (g + 1 < NS) {
            uint32_t sd = aB + ((g + 1) & 1) * 16384 + tid * 64;
            const char* gs = wpl + (size_t)(g + 1) * 16384 + tid * 64;
            CP16(sd, gs); CP16(sd + 16, gs + 16); CP16(sd + 32, gs + 32); CP16(sd + 48, gs + 48);
        }
        CPC;
        if (!XRES && g + 1 < NS) {
            const int kn = ((g + 1) % NPAIR) * 32;
            px[0] = *(const float4*)(xsrc + kn + xo1);
            px[1] = *(const float4*)(xsrc + kn + xo2);
            px[2] = *(const float4*)(xsrc + kn + 16 + xo1);
            px[3] = *(const float4*)(xsrc + kn + 16 + xo2);
        }
        const char* ab = smem + AOFF + (g & 1) * 16384;
#pragma unroll
        for (int p = 0; p < 2; p++) {
            const char* app = ab + p * 8192;
            const char* xb = XRES ? (smem + (s * 2 + p) * 8192)
                                  : (smem + (g & 1) * 16384 + p * 8192);
            uint32_t ah[2][4], al[2][4];
#pragma unroll
            for (int i = 0; i < 2; i++) {
                uint4 q1 = *(const uint4*)(app + aoA[i][0]);
                uint4 q2 = *(const uint4*)(app + aoA[i][1]);
                ah[i][0] = q1.x; ah[i][1] = q2.x; ah[i][2] = q1.y; ah[i][3] = q2.y;
                al[i][0] = q1.z; al[i][1] = q2.z; al[i][2] = q1.w; al[i][3] = q2.w;
            }
            uint4 qb0 = *(const uint4*)(xb + boB[0]);
#pragma unroll
            for (int j = 0; j < 8; j++) {
                uint4 qb1 = qb0;
                if (j < 7) qb1 = *(const uint4*)(xb + boB[j + 1]);
#pragma unroll
                for (int i = 0; i < 2; i++) {
                    mma16(c[i][j], ah[i], qb0.z, qb0.w);
                    mma16(c[i][j], al[i], qb0.x, qb0.y);
                    mma16(c[i][j], ah[i], qb0.x, qb0.y);
                }
                qb0 = qb1;
            }
        }

        if (s == NPAIR - 1) {
            const int mc = g / NPAIR;
#pragma unroll
            for (int i = 0; i < 2; i++) {
                const int chA = mc * 128 + m0 + i * 16 + gq;
                const int chB = chA + 8;
                const float bvA = COLBIAS ? colbias[bb * Mtot + chA] : bias[chA];
                const float bvB = COLBIAS ? colbias[bb * Mtot + chB] : bias[chB];
                float sA = 0.f, qA = 0.f, sB = 0.f, qB = 0.f;
                float mA = -3.4e38f, mB = -3.4e38f;
#pragma unroll
                for (int j = 0; j < 8; j++) {
                    c[i][j][0] += bvA; c[i][j][1] += bvA;
                    c[i][j][2] += bvB; c[i][j][3] += bvB;
                    sA += c[i][j][0] + c[i][j][1];
                    qA = fmaf(c[i][j][0], c[i][j][0], qA);
                    qA = fmaf(c[i][j][1], c[i][j][1], qA);
                    sB += c[i][j][2] + c[i][j][3];
                    qB = fmaf(c[i][j][2], c[i][j][2], qB);
                    qB = fmaf(c[i][j][3], c[i][j][3], qB);
                    if (DOMAX) {
                        mA = fmaxf(mA, fmaxf(c[i][j][0], c[i][j][1]));
                        mB = fmaxf(mB, fmaxf(c[i][j][2], c[i][j][3]));
                    }
                }
#pragma unroll
                for (int o = 1; o <= 2; o <<= 1) {
                    sA += __shfl_xor_sync(0xffffffffu, sA, o);
                    qA += __shfl_xor_sync(0xffffffffu, qA, o);
                    sB += __shfl_xor_sync(0xffffffffu, sB, o);
                    qB += __shfl_xor_sync(0xffffffffu, qB, o);
                    if (DOMAX) {
                        mA = fmaxf(mA, __shfl_xor_sync(0xffffffffu, mA, o));
                        mB = fmaxf(mB, __shfl_xor_sync(0xffffffffu, mB, o));
                    }
                }
                if (t4 == 0) {
                    atomicAdd(&d_sum[statoff + chA], sA);
                    atomicAdd(&d_sq[statoff + chA], qA);
                    atomicAdd(&d_sum[statoff + chB], sB);
                    atomicAdd(&d_sq[statoff + chB], qB);
                    if (DOMAX) {
                        unsigned uA = __float_as_uint(mA);
                        uA = (uA >> 31) ? ~uA : (uA | 0x80000000u);
                        atomicMax(&d_gmax[bb * Mtot + chA], uA);
                        unsigned uB = __float_as_uint(mB);
                        uB = (uB >> 31) ? ~uB : (uB | 0x80000000u);
                        atomicMax(&d_gmax[bb * Mtot + chB], uB);
                    }
                }
                if (STORE) {
#pragma unroll
                    for (int j = 0; j < 8; j++) {
                        float* yp = Y + (size_t)(col0 + n0 + j * 8 + t4 * 2) * Mtot + chA;
                        yp[0] = c[i][j][0];
                        yp[Mtot] = c[i][j][1];
                        yp[8] = c[i][j][2];
                        yp[Mtot + 8] = c[i][j][3];
                    }
                }
#pragma unroll
                for (int j = 0; j < 8; j++)
#pragma unroll
                    for (int k = 0; k < 4; k++) c[i][j][k] = 0.f;
            }
        }
    }
}

// decode max + inline conv3 BN finalize
__global__ void gbn_kernel(const float* __restrict__ g, const float* __restrict__ be) {
    int i = blockIdx.x * 256 + threadIdx.x;
    unsigned u = d_gmax[i];
    float f = (u >> 31) ? __uint_as_float(u & 0x7FFFFFFFu) : __uint_as_float(~u);
    int c = i & 1023;
    float m = d_sum[OFF3 + c] * (1.0f / NCOL);
    float v = d_sq[OFF3 + c] * (1.0f / NCOL) - m * m;
    float sc = g[c] * rsqrtf(v + 1e-5f);
    d_gbn[i] = fmaf(sc, f, fmaf(-m, sc, be[c]));
}

// hvec with k-split x4 (atomic partials; d_hvec zeroed in prep)
__global__ void hvec_kernel(const float* __restrict__ w1, const float* __restrict__ b1) {
    int bbk = blockIdx.x;
    int oc = blockIdx.y * 128 + threadIdx.x;
    int ks = blockIdx.z;
    __shared__ float gb[256];
    for (int i = threadIdx.x; i < 256; i += 128) gb[i] = d_gbn[bbk * 1024 + ks * 256 + i];
    __syncthreads();
    float a = (ks == 0) ? b1[oc] : 0.f;
    const float* wr = w1 + (size_t)oc * 1088 + ks * 256;
#pragma unroll 4
    for (int k = 0; k < 256; k++) a = fmaf(wr[k], gb[k], a);
    atomicAdd(&d_hvec[bbk * 512 + oc], a);
}

// h4: quad-per-column, 64 cols per block, inline h3 BN finalize
__global__ void h4_kernel(const float* __restrict__ w4, const float* __restrict__ b4,
                          const float* __restrict__ g, const float* __restrict__ be,
                          float* __restrict__ out) {
    __shared__ float ws[128], scs[128], shs[128];
    __shared__ int vcnt;
    int tid = threadIdx.x;
    if (tid < 128) {
        ws[tid] = w4[tid];
        float m = d_sum[OFFH3 + tid] * (1.0f / NCOL);
        float v = d_sq[OFFH3 + tid] * (1.0f / NCOL) - m * m;
        float sc = g[tid] * rsqrtf(v + 1e-5f);
        scs[tid] = sc;
        shs[tid] = fmaf(-m, sc, be[tid]);
    }
    if (tid == 0) vcnt = 0;
    __syncthreads();
    const int q = tid >> 2, ql = tid & 3;
    const int col = blockIdx.x * 64 + q;
    const float* src = d_rawh3 + (size_t)col * 128 + ql * 32;
    float a = 0.f;
#pragma unroll
    for (int cch = 0; cch < 8; cch++) {
        float4 x = *(const float4*)(src + cch * 4);
        const int k = ql * 32 + cch * 4;
        a = fmaf(ws[k + 0], fmaxf(fmaf(scs[k + 0], x.x, shs[k + 0]), 0.f), a);
        a = fmaf(ws[k + 1], fmaxf(fmaf(scs[k + 1], x.y, shs[k + 1]), 0.f), a);
        a = fmaf(ws[k + 2], fmaxf(fmaf(scs[k + 2], x.z, shs[k + 2]), 0.f), a);
        a = fmaf(ws[k + 3], fmaxf(fmaf(scs[k + 3], x.w, shs[k + 3]), 0.f), a);
    }
    a += __shfl_xor_sync(0xffffffffu, a, 1);
    a += __shfl_xor_sync(0xffffffffu, a, 2);
    float wv = 1.f + a + __ldg(b4);
    unsigned bal = __ballot_sync(0xffffffffu, (ql == 0) && (wv > 1e-4f));
    if (ql == 0) out[96 + col] = wv;
    if ((tid & 31) == 0) atomicAdd(&vcnt, __popc(bal));
    __syncthreads();
    if (tid == 0) atomicAdd(&d_nv[blockIdx.x >> 5], vcnt);
}

__global__ void solve_kernel(const float* __restrict__ pts, float* __restrict__ out) {
    int bbk = blockIdx.x;
    const float* w = out + 96 + bbk * NPTS;
    const float* px = pts + (size_t)bbk * 3 * NPTS;
    bool usew = d_nv[bbk] > 3;
    float acc[9];
#pragma unroll
    for (int k = 0; k < 9; k++) acc[k] = 0.f;
    for (int n = threadIdx.x; n < NPTS; n += 256) {
        float wv = w[n];
        float we = usew ? ((wv > 1e-4f) ? wv : 0.f) : 1.f;
        float x = px[n], y = px[NPTS + n], z = px[2 * NPTS + n];
        acc[0] = fmaf(we * x, x, acc[0]);
        acc[1] = fmaf(we * x, y, acc[1]);
        acc[2] += we * x;
        acc[3] = fmaf(we * y, y, acc[3]);
        acc[4] += we * y;
        acc[5] += we;
        acc[6] = fmaf(we * x, z, acc[6]);
        acc[7] = fmaf(we * y, z, acc[7]);
        acc[8] = fmaf(we, z, acc[8]);
    }
#pragma unroll
    for (int k = 0; k < 9; k++)
#pragma unroll
        for (int o = 16; o >= 1; o >>= 1) acc[k] += __shfl_xor_sync(0xffffffffu, acc[k], o);
    __shared__ float red[8][9];
    int wid = threadIdx.x >> 5, lane = threadIdx.x & 31;
    if (lane == 0)
        for (int k = 0; k < 9; k++) red[wid][k] = acc[k];
    __syncthreads();
    if (threadIdx.x == 0) {
        float a[9];
        for (int k = 0; k < 9; k++) {
            float s = 0.f;
            for (int i = 0; i < 8; i++) s += red[i][k];
            a[k] = s;
        }
        float L11 = sqrtf(a[0]);
        float L21 = a[1] / L11, L31 = a[2] / L11;
        float L22 = sqrtf(a[3] - L21 * L21);
        float L32 = (a[4] - L31 * L21) / L22;
        float L33 = sqrtf(a[5] - L31 * L31 - L32 * L32);
        float y1 = a[6] / L11;
        float y2 = (a[7] - L21 * y1) / L22;
        float y3 = (a[8] - L31 * y1 - L32 * y2) / L33;
        float be3 = y3 / L33;
        float be2 = (y2 - L32 * be3) / L22;
        float be1 = (y1 - L21 * be2 - L31 * be3) / L11;
        out[bbk * 3 + 0] = be1;
        out[bbk * 3 + 1] = be2;
        out[bbk * 3 + 2] = be3;
    }
}

// ================= launch =================
extern "C" void kernel_launch(void* const* d_in, const int* in_sizes, int n_in,
                              void* d_out, int out_size) {
    const float* pts = (const float*)d_in[0];
    const float* e_w1 = (const float*)d_in[1];
    const float* e_b1 = (const float*)d_in[2];
    const float* e_g1 = (const float*)d_in[3];
    const float* e_be1 = (const float*)d_in[4];
    const float* e_w2 = (const float*)d_in[5];
    const float* e_b2 = (const float*)d_in[6];
    const float* e_g2 = (const float*)d_in[7];
    const float* e_be2 = (const float*)d_in[8];
    const float* e_w3 = (const float*)d_in[9];
    const float* e_b3 = (const float*)d_in[10];
    const float* e_g3 = (const float*)d_in[11];
    const float* e_be3 = (const float*)d_in[12];
    const float* h_w1 = (const float*)d_in[13];
    const float* h_b1 = (const float*)d_in[14];
    const float* h_g1 = (const float*)d_in[15];
    const float* h_be1 = (const float*)d_in[16];
    const float* h_w2 = (const float*)d_in[17];
    const float* h_b2 = (const float*)d_in[18];
    const float* h_g2 = (const float*)d_in[19];
    const float* h_be2 = (const float*)d_in[20];
    const float* h_w3 = (const float*)d_in[21];
    const float* h_b3 = (const float*)d_in[22];
    const float* h_g3 = (const float*)d_in[23];
    const float* h_be3 = (const float*)d_in[24];
    const float* h_w4 = (const float*)d_in[25];
    const float* h_b4 = (const float*)d_in[26];
    float* out = (float*)d_out;

    float *p_raw1, *p_raw2, *p_rawh1, *p_rawh2, *p_rawh3, *p_hvec;
    char* p_wpl;
    cudaGetSymbolAddress((void**)&p_raw1, d_raw1);
    cudaGetSymbolAddress((void**)&p_raw2, d_raw2);
    cudaGetSymbolAddress((void**)&p_rawh1, d_rawh1);
    cudaGetSymbolAddress((void**)&p_rawh2, d_rawh2);
    cudaGetSymbolAddress((void**)&p_rawh3, d_rawh3);
    cudaGetSymbolAddress((void**)&p_hvec, d_hvec);
    cudaGetSymbolAddress((void**)&p_wpl, d_wpl);

    cudaFuncSetAttribute((const void*)mma_kernel<true, true, false, false, 4, 1>,
                         cudaFuncAttributeMaxDynamicSharedMemorySize, 66048);
    cudaFuncSetAttribute((const void*)mma_kernel<true, false, true, false, 8, 8>,
                         cudaFuncAttributeMaxDynamicSharedMemorySize, 99328);
    cudaFuncSetAttribute((const void*)mma_kernel<true, true, false, true, 4, 4>,
                         cudaFuncAttributeMaxDynamicSharedMemorySize, 66048);
    cudaFuncSetAttribute((const void*)mma_kernel<false, true, false, false, 32, 2>,
                         cudaFuncAttributeMaxDynamicSharedMemorySize, 69632);
    cudaFuncSetAttribute((const void*)mma_kernel<false, true, false, false, 16, 1>,
                         cudaFuncAttributeMaxDynamicSharedMemorySize, 67584);

    prep_kernel<<<128, 256>>>(e_w2, e_w3, h_w1, h_w2, h_w3, p_wpl);
    conv1_kernel<<<256, 256>>>(pts, e_w1, e_b1);
    // conv2: 128 x 65536 x 64 (XRES)
    mma_kernel<true, true, false, false, 4, 1><<<512, 256, 66048>>>(
        p_wpl + WOFF_C2, e_b2, e_g1, e_be1, p_raw1, OFF1, p_raw2, OFF2, nullptr);
    // conv3: 1024 x 65536 x 128 (XRES, stats+max only)
    mma_kernel<true, false, true, false, 8, 8><<<512, 256, 99328>>>(
        p_wpl + WOFF_C3, e_b3, e_g2, e_be2, p_raw2, OFF2, nullptr, OFF3, nullptr);
    gbn_kernel<<<128, 256>>>(e_g3, e_be3);
    hvec_kernel<<<dim3(32, 4, 4), 128>>>(h_w1, h_b1);
    // h1 (pointfeat): 512 x 65536 x 64 (XRES, colbias)
    mma_kernel<true, true, false, true, 4, 4><<<512, 256, 66048>>>(
        p_wpl + WOFF_H1, h_b1, e_g1, e_be1, p_raw1, OFF1, p_rawh1, OFFH1, p_hvec);
    // h2: 256 x 65536 x 512 (streaming)
    mma_kernel<false, true, false, false, 32, 2><<<512, 256, 69632>>>(
        p_wpl + WOFF_H2, h_b2, h_g1, h_be1, p_rawh1, OFFH1, p_rawh2, OFFH2, nullptr);
    // h3: 128 x 65536 x 256 (streaming)
    mma_kernel<false, true, false, false, 16, 1><<<512, 256, 67584>>>(
        p_wpl + WOFF_H3, h_b3, h_g2, h_be2, p_rawh2, OFFH2, p_rawh3, OFFH3, nullptr);
    h4_kernel<<<1024, 256>>>(h_w4, h_b4, h_g3, h_be3, out);
    solve_kernel<<<32, 256>>>(pts, out);
}

// round 13
// speedup vs baseline: 1.0116x; 1.0116x over previous
#include <cuda_runtime.h>
#include <cuda_bf16.h>
#include <cstdint>

#define NCOL 65536
#define NB 32
#define NPTS 2048

#define OFF1 0
#define OFF2 64
#define OFF3 192
#define OFFH1 1216
#define OFFH2 1728
#define OFFH3 1984
#define NSTAT 2112

#define WOFF_C2 0
#define WOFF_C3 32768
#define WOFF_H1 557056
#define WOFF_H2 688128
#define WOFF_H3 1212416
#define WPL_TOTAL 1343488

// ---- scratch ----
__device__ float d_raw1[(size_t)NCOL * 64];
__device__ float d_raw2[(size_t)NCOL * 128];
__device__ float d_rawh1[(size_t)NCOL * 512];
__device__ float d_rawh2[(size_t)NCOL * 256];
__device__ float d_rawh3[(size_t)NCOL * 128];
__device__ __align__(16) char d_wpl[WPL_TOTAL];
__device__ float d_sum[NSTAT];
__device__ float d_sq[NSTAT];
__device__ unsigned d_gmax[NB * 1024];
__device__ float d_gbn[NB * 1024];
__device__ float d_hvec[NB * 512];
__device__ int d_nv[NB];

__device__ __forceinline__ uint32_t smem_u32(const void* p) {
    uint32_t a;
    asm("{ .reg .u64 t; cvta.to.shared.u64 t, %1; cvt.u32.u64 %0, t; }" : "=r"(a) : "l"(p));
    return a;
}
#define CP16(sa, ga) \
    asm volatile("cp.async.cg.shared.global [%0], [%1], 16;" ::"r"(sa), "l"(ga) : "memory")
#define CPC asm volatile("cp.async.commit_group;" ::: "memory")
#define CPW0 asm volatile("cp.async.wait_group 0;" ::: "memory")

__device__ __forceinline__ void mma16(float c[4], const uint32_t a[4], uint32_t b0,
                                      uint32_t b1) {
    asm volatile(
        "mma.sync.aligned.m16n8k16.row.col.f32.bf16.bf16.f32 "
        "{%0,%1,%2,%3}, {%4,%5,%6,%7}, {%8,%9}, {%0,%1,%2,%3};"
        : "+f"(c[0]), "+f"(c[1]), "+f"(c[2]), "+f"(c[3])
        : "r"(a[0]), "r"(a[1]), "r"(a[2]), "r"(a[3]), "r"(b0), "r"(b1));
}
// fast hi/lo split of a pair: returns {hi_pair, lo_pair}, v0 -> low half slot
__device__ __forceinline__ uint2 split2(float v0, float v1) {
    uint32_t hp;
    asm("cvt.rn.bf16x2.f32 %0, %1, %2;" : "=r"(hp) : "f"(v1), "f"(v0));
    float h0 = __uint_as_float(hp << 16);
    float h1 = __uint_as_float(hp & 0xFFFF0000u);
    uint32_t lp;
    asm("cvt.rn.bf16x2.f32 %0, %1, %2;" : "=r"(lp) : "f"(v1 - h1), "f"(v0 - h0));
    return make_uint2(hp, lp);
}
// merged hi/lo chunk layout: row = 64B, 4 chunks of 16B, chunk pos ^= (row>>1)&3
__device__ __forceinline__ void split16_merged(const float v[16], char* rowbase, int swz3) {
#pragma unroll
    for (int t = 0; t < 4; t++) {
        uint2 p1 = split2(v[2 * t], v[2 * t + 1]);
        uint2 p2 = split2(v[2 * t + 8], v[2 * t + 9]);
        *(uint4*)(rowbase + ((t ^ swz3) << 4)) = make_uint4(p1.x, p2.x, p1.y, p2.y);
    }
}
// convert 8 activations (chunk-pair grp of a k16 row) and store two merged chunks
__device__ __forceinline__ void conv8_sts(float4 px0, float4 px1, const float* sc,
                                          const float* sh, int xo1, int xo2, char* dx,
                                          int grp, int swz3) {
    float v[8];
    float4 sc0 = *(const float4*)(sc + xo1);
    float4 sh0 = *(const float4*)(sh + xo1);
    float4 sc1 = *(const float4*)(sc + xo2);
    float4 sh1 = *(const float4*)(sh + xo2);
    v[0] = fmaxf(fmaf(sc0.x, px0.x, sh0.x), 0.f);
    v[1] = fmaxf(fmaf(sc0.y, px0.y, sh0.y), 0.f);
    v[2] = fmaxf(fmaf(sc0.z, px0.z, sh0.z), 0.f);
    v[3] = fmaxf(fmaf(sc0.w, px0.w, sh0.w), 0.f);
    v[4] = fmaxf(fmaf(sc1.x, px1.x, sh1.x), 0.f);
    v[5] = fmaxf(fmaf(sc1.y, px1.y, sh1.y), 0.f);
    v[6] = fmaxf(fmaf(sc1.z, px1.z, sh1.z), 0.f);
    v[7] = fmaxf(fmaf(sc1.w, px1.w, sh1.w), 0.f);
    uint2 s01 = split2(v[0], v[1]);
    uint2 s45 = split2(v[4], v[5]);
    uint2 s23 = split2(v[2], v[3]);
    uint2 s67 = split2(v[6], v[7]);
    *(uint4*)(dx + (((grp * 2) ^ swz3) << 4)) = make_uint4(s01.x, s45.x, s01.y, s45.y);
    *(uint4*)(dx + (((grp * 2 + 1) ^ swz3) << 4)) = make_uint4(s23.x, s67.x, s23.y, s67.y);
}

// ===== prep: zero counters + split all weights into merged bf16 planes =====
__global__ void prep_kernel(const float* __restrict__ w2, const float* __restrict__ w3,
                            const float* __restrict__ hw1, const float* __restrict__ hw2,
                            const float* __restrict__ hw3, char* __restrict__ dst) {
    int idx = blockIdx.x * 256 + threadIdx.x;
    if (idx < NSTAT) { d_sum[idx] = 0.f; d_sq[idx] = 0.f; }
    if (idx < NB * 1024) d_gmax[idx] = 0u;
    if (idx < NB * 512) d_hvec[idx] = 0.f;
    if (idx < NB) d_nv[idx] = 0;

    const float* W; int lda, woff, Cin; char* d; int li;
    if (idx < 512) { W = w2; lda = 64; woff = 0; Cin = 64; d = dst + WOFF_C2; li = idx; }
    else if (idx < 8704) { W = w3; lda = 128; woff = 0; Cin = 128; d = dst + WOFF_C3; li = idx - 512; }
    else if (idx < 10752) { W = hw1; lda = 1088; woff = 1024; Cin = 64; d = dst + WOFF_H1; li = idx - 8704; }
    else if (idx < 18944) { W = hw2; lda = 512; woff = 0; Cin = 512; d = dst + WOFF_H2; li = idx - 10752; }
    else if (idx < 20992) { W = hw3; lda = 256; woff = 0; Cin = 256; d = dst + WOFF_H3; li = idx - 18944; }
    else return;
    const int TK = Cin >> 4;
    const int m = li / TK, k16 = li % TK;
    const float* src = W + (size_t)m * lda + woff + k16 * 16;
    float v[16];
#pragma unroll
    for (int q = 0; q < 4; q++) {
        float4 f = *(const float4*)(src + q * 4);
        v[q * 4 + 0] = f.x; v[q * 4 + 1] = f.y; v[q * 4 + 2] = f.z; v[q * 4 + 3] = f.w;
    }
    const int row = m & 127;
    char* base = d + (size_t)((m >> 7) * TK + k16) * 8192 + row * 64;
    split16_merged(v, base, (row >> 1) & 3);
}

// conv1: 3 -> 64, transposed out [col][64], fused stats
__global__ void conv1_kernel(const float* __restrict__ pts,
                             const float* __restrict__ w,
                             const float* __restrict__ b) {
    __shared__ float ws[192], bs[64], bsum[64], bsq[64];
    int tid = threadIdx.x;
    if (tid < 192) ws[tid] = w[tid];
    if (tid < 64) { bs[tid] = b[tid]; bsum[tid] = 0.f; bsq[tid] = 0.f; }
    __syncthreads();
    int wid = tid >> 5, lid = tid & 31;
    int colbase = (blockIdx.x * 8 + wid) * 32;
    int bb = colbase >> 11, n = colbase & 2047;
    const float* p = pts + (size_t)bb * 3 * NPTS + n + lid;
    float p0 = p[0], p1 = p[NPTS], p2 = p[2 * NPTS];
    float wa0 = ws[lid * 3], wa1 = ws[lid * 3 + 1], wa2 = ws[lid * 3 + 2];
    float wb0 = ws[(lid + 32) * 3], wb1 = ws[(lid + 32) * 3 + 1], wb2 = ws[(lid + 32) * 3 + 2];
    float ba = bs[lid], bbv = bs[lid + 32];
    float sa = 0.f, qa = 0.f, sb = 0.f, qb = 0.f;
#pragma unroll 8
    for (int c = 0; c < 32; c++) {
        float x = __shfl_sync(0xffffffffu, p0, c);
        float y = __shfl_sync(0xffffffffu, p1, c);
        float z = __shfl_sync(0xffffffffu, p2, c);
        float va = fmaf(wa0, x, fmaf(wa1, y, fmaf(wa2, z, ba)));
        float vb = fmaf(wb0, x, fmaf(wb1, y, fmaf(wb2, z, bbv)));
        d_raw1[(size_t)(colbase + c) * 64 + lid] = va;
        d_raw1[(size_t)(colbase + c) * 64 + 32 + lid] = vb;
        sa += va; qa = fmaf(va, va, qa);
        sb += vb; qb = fmaf(vb, vb, qb);
    }
    atomicAdd(&bsum[lid], sa); atomicAdd(&bsq[lid], qa);
    atomicAdd(&bsum[32 + lid], sb); atomicAdd(&bsq[32 + lid], qb);
    __syncthreads();
    if (tid < 64) {
        atomicAdd(&d_sum[OFF1 + tid], bsum[tid]);
        atomicAdd(&d_sq[OFF1 + tid], bsq[tid]);
    }
}

// ========== 3-CTA/SM XRES GEMM: 64 cols/CTA, warp tile 32x32, 32 accums ==========
// X planes @0 (TK*4096), A slots @AOFF (2x16384), sc/sh @AOFF+32768.
template <bool STORE, bool DOMAX, bool COLBIAS, int TK, int MC>
__global__ void __launch_bounds__(256, 3) mma3_kernel(
    const char* __restrict__ wpl, const float* __restrict__ bias,
    const float* __restrict__ gg_, const float* __restrict__ be,
    const float* __restrict__ Xraw, int actoff,
    float* __restrict__ Y, int statoff,
    const float* __restrict__ colbias) {
    extern __shared__ __align__(16) char smem[];
    constexpr int Cin = TK * 16;
    constexpr int Mtot = MC * 128;
    constexpr int NPAIR = TK / 2;
    constexpr int NS = MC * NPAIR;
    constexpr int AOFF = TK * 4096;
    const int tid = threadIdx.x;
    const int wid = tid >> 5, lane = tid & 31;
    const int gq = lane >> 2, t4 = lane & 3;
    const int m0 = (wid & 3) * 32;
    const int n0 = (wid >> 2) * 32;
    const int col0 = blockIdx.x * 64;
    const int bb = col0 >> 11;
    const uint32_t aB = smem_u32(smem) + AOFF;
    float* sc_s = (float*)(smem + AOFF + 32768);
    float* sh_s = sc_s + Cin;

    // preamble: stage 0 cp.async
    {
        uint32_t s0 = aB + tid * 64;
        const char* g0 = wpl + tid * 64;
        CP16(s0, g0); CP16(s0 + 16, g0 + 16); CP16(s0 + 32, g0 + 32); CP16(s0 + 48, g0 + 48);
        CPC;
    }
    // inline BN finalize
    for (int k = tid; k < Cin; k += 256) {
        float m = d_sum[actoff + k] * (1.0f / NCOL);
        float v = d_sq[actoff + k] * (1.0f / NCOL) - m * m;
        float sc = gg_[k] * rsqrtf(v + 1e-5f);
        sc_s[k] = sc;
        sh_s[k] = fmaf(-m, sc, be[k]);
    }
    __syncthreads();

    // X conversion: row6 = tid&63, grp = (tid>>6)&1 (chunk pair), kk = tid>>7 (k16 parity)
    {
        const int row6 = tid & 63;
        const int grp = (tid >> 6) & 1;
        const int kk = tid >> 7;
        const int swz3 = (row6 >> 1) & 3;
        const float* xsrc = Xraw + (size_t)(col0 + row6) * Cin;
        for (int k16 = kk; k16 < TK; k16 += 2) {
            float4 p0 = *(const float4*)(xsrc + k16 * 16 + grp * 4);
            float4 p1 = *(const float4*)(xsrc + k16 * 16 + grp * 4 + 8);
            conv8_sts(p0, p1, sc_s + k16 * 16, sh_s + k16 * 16, grp * 4, grp * 4 + 8,
                      smem + k16 * 4096 + row6 * 64, grp, swz3);
        }
    }

    uint32_t aoA[2][2], boB[4];
#pragma unroll
    for (int i = 0; i < 2; i++) {
        const int r1 = m0 + i * 16 + gq, r2 = r1 + 8;
        aoA[i][0] = r1 * 64 + ((t4 ^ ((r1 >> 1) & 3)) << 4);
        aoA[i][1] = r2 * 64 + ((t4 ^ ((r2 >> 1) & 3)) << 4);
    }
#pragma unroll
    for (int j = 0; j < 4; j++) {
        const int rb = n0 + j * 8 + gq;
        boB[j] = rb * 64 + ((t4 ^ ((rb >> 1) & 3)) << 4);
    }

    float c[2][4][4];
#pragma unroll
    for (int i = 0; i < 2; i++)
#pragma unroll
        for (int j = 0; j < 4; j++)
#pragma unroll
            for (int k = 0; k < 4; k++) c[i][j][k] = 0.f;

    for (int g = 0; g < NS; g++) {
        const int s = g % NPAIR;
        CPW0;
        __syncthreads();  // publishes A stage g (+ X conversion at g=0)
        if (g + 1 < NS) {
            uint32_t sd = aB + ((g + 1) & 1) * 16384 + tid * 64;
            const char* gs = wpl + (size_t)(g + 1) * 16384 + tid * 64;
            CP16(sd, gs); CP16(sd + 16, gs + 16); CP16(sd + 32, gs + 32); CP16(sd + 48, gs + 48);
        }
        CPC;
        const char* ab = smem + AOFF + (g & 1) * 16384;
#pragma unroll
        for (int p = 0; p < 2; p++) {
            const char* app = ab + p * 8192;
            const char* xb = smem + (s * 2 + p) * 4096;
            uint32_t ah[2][4], al[2][4];
#pragma unroll
            for (int i = 0; i < 2; i++) {
                uint4 q1 = *(const uint4*)(app + aoA[i][0]);
                uint4 q2 = *(const uint4*)(app + aoA[i][1]);
                ah[i][0] = q1.x; ah[i][1] = q2.x; ah[i][2] = q1.y; ah[i][3] = q2.y;
                al[i][0] = q1.z; al[i][1] = q2.z; al[i][2] = q1.w; al[i][3] = q2.w;
            }
            uint4 qb0 = *(const uint4*)(xb + boB[0]);
#pragma unroll
            for (int j = 0; j < 4; j++) {
                uint4 qb1 = qb0;
                if (j < 3) qb1 = *(const uint4*)(xb + boB[j + 1]);
#pragma unroll
                for (int i = 0; i < 2; i++) {
                    mma16(c[i][j], ah[i], qb0.z, qb0.w);
                    mma16(c[i][j], al[i], qb0.x, qb0.y);
                    mma16(c[i][j], ah[i], qb0.x, qb0.y);
                }
                qb0 = qb1;
            }
        }

        if (s == NPAIR - 1) {  // ---- per-mc epilogue ----
            const int mc = g / NPAIR;
#pragma unroll
            for (int i = 0; i < 2; i++) {
                const int chA = mc * 128 + m0 + i * 16 + gq;
                const int chB = chA + 8;
                const float bvA = COLBIAS ? colbias[bb * Mtot + chA] : bias[chA];
                const float bvB = COLBIAS ? colbias[bb * Mtot + chB] : bias[chB];
                float sA = 0.f, qA = 0.f, sB = 0.f, qB = 0.f;
                float mA = -3.4e38f, mB = -3.4e38f;
#pragma unroll
                for (int j = 0; j < 4; j++) {
                    c[i][j][0] += bvA; c[i][j][1] += bvA;
                    c[i][j][2] += bvB; c[i][j][3] += bvB;
                    sA += c[i][j][0] + c[i][j][1];
                    qA = fmaf(c[i][j][0], c[i][j][0], qA);
                    qA = fmaf(c[i][j][1], c[i][j][1], qA);
                    sB += c[i][j][2] + c[i][j][3];
                    qB = fmaf(c[i][j][2], c[i][j][2], qB);
                    qB = fmaf(c[i][j][3], c[i][j][3], qB);
                    if (DOMAX) {
                        mA = fmaxf(mA, fmaxf(c[i][j][0], c[i][j][1]));
                        mB = fmaxf(mB, fmaxf(c[i][j][2], c[i][j][3]));
                    }
                }
#pragma unroll
                for (int o = 1; o <= 2; o <<= 1) {
                    sA += __shfl_xor_sync(0xffffffffu, sA, o);
                    qA += __shfl_xor_sync(0xffffffffu, qA, o);
                    sB += __shfl_xor_sync(0xffffffffu, sB, o);
                    qB += __shfl_xor_sync(0xffffffffu, qB, o);
                    if (DOMAX) {
                        mA = fmaxf(mA, __shfl_xor_sync(0xffffffffu, mA, o));
                        mB = fmaxf(mB, __shfl_xor_sync(0xffffffffu, mB, o));
                    }
                }
                if (t4 == 0) {
                    atomicAdd(&d_sum[statoff + chA], sA);
                    atomicAdd(&d_sq[statoff + chA], qA);
                    atomicAdd(&d_sum[statoff + chB], sB);
                    atomicAdd(&d_sq[statoff + chB], qB);
                    if (DOMAX) {
                        unsigned uA = __float_as_uint(mA);
                        uA = (uA >> 31) ? ~uA : (uA | 0x80000000u);
                        atomicMax(&d_gmax[bb * Mtot + chA], uA);
                        unsigned uB = __float_as_uint(mB);
                        uB = (uB >> 31) ? ~uB : (uB | 0x80000000u);
                        atomicMax(&d_gmax[bb * Mtot + chB], uB);
                    }
                }
                if (STORE) {
#pragma unroll
                    for (int j = 0; j < 4; j++) {
                        float* yp = Y + (size_t)(col0 + n0 + j * 8 + t4 * 2) * Mtot + chA;
                        yp[0] = c[i][j][0];
                        yp[Mtot] = c[i][j][1];
                        yp[8] = c[i][j][2];
                        yp[Mtot + 8] = c[i][j][3];
                    }
                }
#pragma unroll
                for (int j = 0; j < 4; j++)
#pragma unroll
                    for (int k = 0; k < 4; k++) c[i][j][k] = 0.f;
            }
        }
    }
}

// ========== streaming GEMM (h2/h3): 128 cols/CTA, 2 CTAs/SM (validated) ==========
template <bool STORE, bool DOMAX, bool COLBIAS, int TK, int MC>
__global__ void __launch_bounds__(256, 2) mma_kernel(
    const char* __restrict__ wpl, const float* __restrict__ bias,
    const float* __restrict__ gg_, const float* __restrict__ be,
    const float* __restrict__ Xraw, int actoff,
    float* __restrict__ Y, int statoff,
    const float* __restrict__ colbias) {
    extern __shared__ __align__(16) char smem[];
    constexpr int Cin = TK * 16;
    constexpr int Mtot = MC * 128;
    constexpr int NPAIR = TK / 2;
    constexpr int NS = MC * NPAIR;
    constexpr int AOFF = 32768;
    const int tid = threadIdx.x;
    const int wid = tid >> 5, lane = tid & 31;
    const int gq = lane >> 2, t4 = lane & 3;
    const int m0 = (wid & 3) * 32;
    const int n0 = (wid >> 2) * 64;
    const int col0 = blockIdx.x * 128;
    const int bb = col0 >> 11;
    const uint32_t aB = smem_u32(smem) + AOFF;
    float* sc_s = (float*)(smem + AOFF + 32768);
    float* sh_s = sc_s + Cin;

    {
        uint32_t s0 = aB + tid * 64;
        const char* g0 = wpl + tid * 64;
        CP16(s0, g0); CP16(s0 + 16, g0 + 16); CP16(s0 + 32, g0 + 32); CP16(s0 + 48, g0 + 48);
        CPC;
    }
    for (int k = tid; k < Cin; k += 256) {
        float m = d_sum[actoff + k] * (1.0f / NCOL);
        float v = d_sq[actoff + k] * (1.0f / NCOL) - m * m;
        float sc = gg_[k] * rsqrtf(v + 1e-5f);
        sc_s[k] = sc;
        sh_s[k] = fmaf(-m, sc, be[k]);
    }
    __syncthreads();

    const int row = tid & 127;
    const int grp = tid >> 7;
    const int swz3 = (row >> 1) & 3;
    const float* xsrc = Xraw + (size_t)(col0 + row) * Cin;
    const int xo1 = grp * 4, xo2 = grp * 4 + 8;

    uint32_t aoA[2][2], boB[8];
#pragma unroll
    for (int i = 0; i < 2; i++) {
        const int r1 = m0 + i * 16 + gq, r2 = r1 + 8;
        aoA[i][0] = r1 * 64 + ((t4 ^ ((r1 >> 1) & 3)) << 4);
        aoA[i][1] = r2 * 64 + ((t4 ^ ((r2 >> 1) & 3)) << 4);
    }
#pragma unroll
    for (int j = 0; j < 8; j++) {
        const int rb = n0 + j * 8 + gq;
        boB[j] = rb * 64 + ((t4 ^ ((rb >> 1) & 3)) << 4);
    }

    float c[2][8][4];
#pragma unroll
    for (int i = 0; i < 2; i++)
#pragma unroll
        for (int j = 0; j < 8; j++)
#pragma unroll
            for (int k = 0; k < 4; k++) c[i][j][k] = 0.f;

    float4 px[4];
    px[0] = *(const float4*)(xsrc + xo1);
    px[1] = *(const float4*)(xsrc + xo2);
    px[2] = *(const float4*)(xsrc + 16 + xo1);
    px[3] = *(const float4*)(xsrc + 16 + xo2);

    for (int g = 0; g < NS; g++) {
        const int s = g % NPAIR;
        {
            const int kb = s * 32;
            char* dx = smem + (g & 1) * 16384 + row * 64;
            conv8_sts(px[0], px[1], sc_s + kb, sh_s + kb, xo1, xo2, dx, grp, swz3);
            conv8_sts(px[2], px[3], sc_s + kb + 16, sh_s + kb + 16, xo1, xo2, dx + 8192, grp, swz3);
        }
        CPW0;
        __syncthreads();
        if (g + 1 < NS) {
            uint32_t sd = aB + ((g + 1) & 1) * 16384 + tid * 64;
            const char* gs = wpl + (size_t)(g + 1) * 16384 + tid * 64;
            CP16(sd, gs); CP16(sd + 16, gs + 16); CP16(sd + 32, gs + 32); CP16(sd + 48, gs + 48);
        }
        CPC;
        if (g + 1 < NS) {
            const int kn = ((g + 1) % NPAIR) * 32;
            px[0] = *(const float4*)(xsrc + kn + xo1);
            px[1] = *(const float4*)(xsrc + kn + xo2);
            px[2] = *(const float4*)(xsrc + kn + 16 + xo1);
            px[3] = *(const float4*)(xsrc + kn + 16 + xo2);
        }
        const char* ab = smem + AOFF + (g & 1) * 16384;
#pragma unroll
        for (int p = 0; p < 2; p++) {
            const char* app = ab + p * 8192;
            const char* xb = smem + (g & 1) * 16384 + p * 8192;
            uint32_t ah[2][4], al[2][4];
#pragma unroll
            for (int i = 0; i < 2; i++) {
                uint4 q1 = *(const uint4*)(app + aoA[i][0]);
                uint4 q2 = *(const uint4*)(app + aoA[i][1]);
                ah[i][0] = q1.x; ah[i][1] = q2.x; ah[i][2] = q1.y; ah[i][3] = q2.y;
                al[i][0] = q1.z; al[i][1] = q2.z; al[i][2] = q1.w; al[i][3] = q2.w;
            }
            uint4 qb0 = *(const uint4*)(xb + boB[0]);
#pragma unroll
            for (int j = 0; j < 8; j++) {
                uint4 qb1 = qb0;
                if (j < 7) qb1 = *(const uint4*)(xb + boB[j + 1]);
#pragma unroll
                for (int i = 0; i < 2; i++) {
                    mma16(c[i][j], ah[i], qb0.z, qb0.w);
                    mma16(c[i][j], al[i], qb0.x, qb0.y);
                    mma16(c[i][j], ah[i], qb0.x, qb0.y);
                }
                qb0 = qb1;
            }
        }

        if (s == NPAIR - 1) {
            const int mc = g / NPAIR;
#pragma unroll
            for (int i = 0; i < 2; i++) {
                const int chA = mc * 128 + m0 + i * 16 + gq;
                const int chB = chA + 8;
                const float bvA = COLBIAS ? colbias[bb * Mtot + chA] : bias[chA];
                const float bvB = COLBIAS ? colbias[bb * Mtot + chB] : bias[chB];
                float sA = 0.f, qA = 0.f, sB = 0.f, qB = 0.f;
                float mA = -3.4e38f, mB = -3.4e38f;
#pragma unroll
                for (int j = 0; j < 8; j++) {
                    c[i][j][0] += bvA; c[i][j][1] += bvA;
                    c[i][j][2] += bvB; c[i][j][3] += bvB;
                    sA += c[i][j][0] + c[i][j][1];
                    qA = fmaf(c[i][j][0], c[i][j][0], qA);
                    qA = fmaf(c[i][j][1], c[i][j][1], qA);
                    sB += c[i][j][2] + c[i][j][3];
                    qB = fmaf(c[i][j][2], c[i][j][2], qB);
                    qB = fmaf(c[i][j][3], c[i][j][3], qB);
                    if (DOMAX) {
                        mA = fmaxf(mA, fmaxf(c[i][j][0], c[i][j][1]));
                        mB = fmaxf(mB, fmaxf(c[i][j][2], c[i][j][3]));
                    }
                }
#pragma unroll
                for (int o = 1; o <= 2; o <<= 1) {
                    sA += __shfl_xor_sync(0xffffffffu, sA, o);
                    qA += __shfl_xor_sync(0xffffffffu, qA, o);
                    sB += __shfl_xor_sync(0xffffffffu, sB, o);
                    qB += __shfl_xor_sync(0xffffffffu, qB, o);
                    if (DOMAX) {
                        mA = fmaxf(mA, __shfl_xor_sync(0xffffffffu, mA, o));
                        mB = fmaxf(mB, __shfl_xor_sync(0xffffffffu, mB, o));
                    }
                }
                if (t4 == 0) {
                    atomicAdd(&d_sum[statoff + chA], sA);
                    atomicAdd(&d_sq[statoff + chA], qA);
                    atomicAdd(&d_sum[statoff + chB], sB);
                    atomicAdd(&d_sq[statoff + chB], qB);
                    if (DOMAX) {
                        unsigned uA = __float_as_uint(mA);
                        uA = (uA >> 31) ? ~uA : (uA | 0x80000000u);
                        atomicMax(&d_gmax[bb * Mtot + chA], uA);
                        unsigned uB = __float_as_uint(mB);
                        uB = (uB >> 31) ? ~uB : (uB | 0x80000000u);
                        atomicMax(&d_gmax[bb * Mtot + chB], uB);
                    }
                }
                if (STORE) {
#pragma unroll
                    for (int j = 0; j < 8; j++) {
                        float* yp = Y + (size_t)(col0 + n0 + j * 8 + t4 * 2) * Mtot + chA;
                        yp[0] = c[i][j][0];
                        yp[Mtot] = c[i][j][1];
                        yp[8] = c[i][j][2];
                        yp[Mtot + 8] = c[i][j][3];
                    }
                }
#pragma unroll
                for (int j = 0; j < 8; j++)
#pragma unroll
                    for (int k = 0; k < 4; k++) c[i][j][k] = 0.f;
            }
        }
    }
}

// decode max + inline conv3 BN finalize
__global__ void gbn_kernel(const float* __restrict__ g, const float* __restrict__ be) {
    int i = blockIdx.x * 256 + threadIdx.x;
    unsigned u = d_gmax[i];
    float f = (u >> 31) ? __uint_as_float(u & 0x7FFFFFFFu) : __uint_as_float(~u);
    int c = i & 1023;
    float m = d_sum[OFF3 + c] * (1.0f / NCOL);
    float v = d_sq[OFF3 + c] * (1.0f / NCOL) - m * m;
    float sc = g[c] * rsqrtf(v + 1e-5f);
    d_gbn[i] = fmaf(sc, f, fmaf(-m, sc, be[c]));
}

// hvec with k-split x4
__global__ void hvec_kernel(const float* __restrict__ w1, const float* __restrict__ b1) {
    int bbk = blockIdx.x;
    int oc = blockIdx.y * 128 + threadIdx.x;
    int ks = blockIdx.z;
    __shared__ float gb[256];
    for (int i = threadIdx.x; i < 256; i += 128) gb[i] = d_gbn[bbk * 1024 + ks * 256 + i];
    __syncthreads();
    float a = (ks == 0) ? b1[oc] : 0.f;
    const float* wr = w1 + (size_t)oc * 1088 + ks * 256;
#pragma unroll 4
    for (int k = 0; k < 256; k++) a = fmaf(wr[k], gb[k], a);
    atomicAdd(&d_hvec[bbk * 512 + oc], a);
}

// h4: quad-per-column, 64 cols per block, inline h3 BN finalize
__global__ void h4_kernel(const float* __restrict__ w4, const float* __restrict__ b4,
                          const float* __restrict__ g, const float* __restrict__ be,
                          float* __restrict__ out) {
    __shared__ float ws[128], scs[128], shs[128];
    __shared__ int vcnt;
    int tid = threadIdx.x;
    if (tid < 128) {
        ws[tid] = w4[tid];
        float m = d_sum[OFFH3 + tid] * (1.0f / NCOL);
        float v = d_sq[OFFH3 + tid] * (1.0f / NCOL) - m * m;
        float sc = g[tid] * rsqrtf(v + 1e-5f);
        scs[tid] = sc;
        shs[tid] = fmaf(-m, sc, be[tid]);
    }
    if (tid == 0) vcnt = 0;
    __syncthreads();
    const int q = tid >> 2, ql = tid & 3;
    const int col = blockIdx.x * 64 + q;
    const float* src = d_rawh3 + (size_t)col * 128 + ql * 32;
    float a = 0.f;
#pragma unroll
    for (int cch = 0; cch < 8; cch++) {
        float4 x = *(const float4*)(src + cch * 4);
        const int k = ql * 32 + cch * 4;
        a = fmaf(ws[k + 0], fmaxf(fmaf(scs[k + 0], x.x, shs[k + 0]), 0.f), a);
        a = fmaf(ws[k + 1], fmaxf(fmaf(scs[k + 1], x.y, shs[k + 1]), 0.f), a);
        a = fmaf(ws[k + 2], fmaxf(fmaf(scs[k + 2], x.z, shs[k + 2]), 0.f), a);
        a = fmaf(ws[k + 3], fmaxf(fmaf(scs[k + 3], x.w, shs[k + 3]), 0.f), a);
    }
    a += __shfl_xor_sync(0xffffffffu, a, 1);
    a += __shfl_xor_sync(0xffffffffu, a, 2);
    float wv = 1.f + a + __ldg(b4);
    unsigned bal = __ballot_sync(0xffffffffu, (ql == 0) && (wv > 1e-4f));
    if (ql == 0) out[96 + col] = wv;
    if ((tid & 31) == 0) atomicAdd(&vcnt, __popc(bal));
    __syncthreads();
    if (tid == 0) atomicAdd(&d_nv[blockIdx.x >> 5], vcnt);
}

__global__ void solve_kernel(const float* __restrict__ pts, float* __restrict__ out) {
    int bbk = blockIdx.x;
    const float* w = out + 96 + bbk * NPTS;
    const float* px = pts + (size_t)bbk * 3 * NPTS;
    bool usew = d_nv[bbk] > 3;
    float acc[9];
#pragma unroll
    for (int k = 0; k < 9; k++) acc[k] = 0.f;
    for (int n = threadIdx.x; n < NPTS; n += 256) {
        float wv = w[n];
        float we = usew ? ((wv > 1e-4f) ? wv : 0.f) : 1.f;
        float x = px[n], y = px[NPTS + n], z = px[2 * NPTS + n];
        acc[0] = fmaf(we * x, x, acc[0]);
        acc[1] = fmaf(we * x, y, acc[1]);
        acc[2] += we * x;
        acc[3] = fmaf(we * y, y, acc[3]);
        acc[4] += we * y;
        acc[5] += we;
        acc[6] = fmaf(we * x, z, acc[6]);
        acc[7] = fmaf(we * y, z, acc[7]);
        acc[8] = fmaf(we, z, acc[8]);
    }
#pragma unroll
    for (int k = 0; k < 9; k++)
#pragma unroll
        for (int o = 16; o >= 1; o >>= 1) acc[k] += __shfl_xor_sync(0xffffffffu, acc[k], o);
    __shared__ float red[8][9];
    int wid = threadIdx.x >> 5, lane = threadIdx.x & 31;
    if (lane == 0)
        for (int k = 0; k < 9; k++) red[wid][k] = acc[k];
    __syncthreads();
    if (threadIdx.x == 0) {
        float a[9];
        for (int k = 0; k < 9; k++) {
            float s = 0.f;
            for (int i = 0; i < 8; i++) s += red[i][k];
            a[k] = s;
        }
        float L11 = sqrtf(a[0]);
        float L21 = a[1] / L11, L31 = a[2] / L11;
        float L22 = sqrtf(a[3] - L21 * L21);
        float L32 = (a[4] - L31 * L21) / L22;
        float L33 = sqrtf(a[5] - L31 * L31 - L32 * L32);
        float y1 = a[6] / L11;
        float y2 = (a[7] - L21 * y1) / L22;
        float y3 = (a[8] - L31 * y1 - L32 * y2) / L33;
        float be3 = y3 / L33;
        float be2 = (y2 - L32 * be3) / L22;
        float be1 = (y1 - L21 * be2 - L31 * be3) / L11;
        out[bbk * 3 + 0] = be1;
        out[bbk * 3 + 1] = be2;
        out[bbk * 3 + 2] = be3;
    }
}

// ================= launch =================
extern "C" void kernel_launch(void* const* d_in, const int* in_sizes, int n_in,
                              void* d_out, int out_size) {
    const float* pts = (const float*)d_in[0];
    const float* e_w1 = (const float*)d_in[1];
    const float* e_b1 = (const float*)d_in[2];
    const float* e_g1 = (const float*)d_in[3];
    const float* e_be1 = (const float*)d_in[4];
    const float* e_w2 = (const float*)d_in[5];
    const float* e_b2 = (const float*)d_in[6];
    const float* e_g2 = (const float*)d_in[7];
    const float* e_be2 = (const float*)d_in[8];
    const float* e_w3 = (const float*)d_in[9];
    const float* e_b3 = (const float*)d_in[10];
    const float* e_g3 = (const float*)d_in[11];
    const float* e_be3 = (const float*)d_in[12];
    const float* h_w1 = (const float*)d_in[13];
    const float* h_b1 = (const float*)d_in[14];
    const float* h_g1 = (const float*)d_in[15];
    const float* h_be1 = (const float*)d_in[16];
    const float* h_w2 = (const float*)d_in[17];
    const float* h_b2 = (const float*)d_in[18];
    const float* h_g2 = (const float*)d_in[19];
    const float* h_be2 = (const float*)d_in[20];
    const float* h_w3 = (const float*)d_in[21];
    const float* h_b3 = (const float*)d_in[22];
    const float* h_g3 = (const float*)d_in[23];
    const float* h_be3 = (const float*)d_in[24];
    const float* h_w4 = (const float*)d_in[25];
    const float* h_b4 = (const float*)d_in[26];
    float* out = (float*)d_out;

    float *p_raw1, *p_raw2, *p_rawh1, *p_rawh2, *p_rawh3, *p_hvec;
    char* p_wpl;
    cudaGetSymbolAddress((void**)&p_raw1, d_raw1);
    cudaGetSymbolAddress((void**)&p_raw2, d_raw2);
    cudaGetSymbolAddress((void**)&p_rawh1, d_rawh1);
    cudaGetSymbolAddress((void**)&p_rawh2, d_rawh2);
    cudaGetSymbolAddress((void**)&p_rawh3, d_rawh3);
    cudaGetSymbolAddress((void**)&p_hvec, d_hvec);
    cudaGetSymbolAddress((void**)&p_wpl, d_wpl);

    // mma3 smem: TK*4096 + 32768 + 8*Cin
    cudaFuncSetAttribute((const void*)mma3_kernel<true, false, false, 4, 1>,
                         cudaFuncAttributeMaxDynamicSharedMemorySize, 49664);
    cudaFuncSetAttribute((const void*)mma3_kernel<false, true, false, 8, 8>,
                         cudaFuncAttributeMaxDynamicSharedMemorySize, 66560);
    cudaFuncSetAttribute((const void*)mma3_kernel<true, false, true, 4, 4>,
                         cudaFuncAttributeMaxDynamicSharedMemorySize, 49664);
    // streaming smem: 65536 + 8*Cin
    cudaFuncSetAttribute((const void*)mma_kernel<true, false, false, 32, 2>,
                         cudaFuncAttributeMaxDynamicSharedMemorySize, 69632);
    cudaFuncSetAttribute((const void*)mma_kernel<true, false, false, 16, 1>,
                         cudaFuncAttributeMaxDynamicSharedMemorySize, 67584);

    prep_kernel<<<128, 256>>>(e_w2, e_w3, h_w1, h_w2, h_w3, p_wpl);
    conv1_kernel<<<256, 256>>>(pts, e_w1, e_b1);
    // conv2: 128 x 65536 x 64 (3-CTA XRES)
    mma3_kernel<true, false, false, 4, 1><<<1024, 256, 49664>>>(
        p_wpl + WOFF_C2, e_b2, e_g1, e_be1, p_raw1, OFF1, p_raw2, OFF2, nullptr);
    // conv3: 1024 x 65536 x 128 (3-CTA XRES, stats+max only)
    mma3_kernel<false, true, false, 8, 8><<<1024, 256, 66560>>>(
        p_wpl + WOFF_C3, e_b3, e_g2, e_be2, p_raw2, OFF2, nullptr, OFF3, nullptr);
    gbn_kernel<<<128, 256>>>(e_g3, e_be3);
    hvec_kernel<<<dim3(32, 4, 4), 128>>>(h_w1, h_b1);
    // h1 (pointfeat): 512 x 65536 x 64 (3-CTA XRES, colbias)
    mma3_kernel<true, false, true, 4, 4><<<1024, 256, 49664>>>(
        p_wpl + WOFF_H1, h_b1, e_g1, e_be1, p_raw1, OFF1, p_rawh1, OFFH1, p_hvec);
    // h2: 256 x 65536 x 512 (streaming)
    mma_kernel<true, false, false, 32, 2><<<512, 256, 69632>>>(
        p_wpl + WOFF_H2, h_b2, h_g1, h_be1, p_rawh1, OFFH1, p_rawh2, OFFH2, nullptr);
    // h3: 128 x 65536 x 256 (streaming)
    mma_kernel<true, false, false, 16, 1><<<512, 256, 67584>>>(
        p_wpl + WOFF_H3, h_b3, h_g2, h_be2, p_rawh2, OFFH2, p_rawh3, OFFH3, nullptr);
    h4_kernel<<<1024, 256>>>(h_w4, h_b4, h_g3, h_be3, out);
    solve_kernel<<<32, 256>>>(pts, out);
}